// round 4
// baseline (speedup 1.0000x reference)
#include <cuda_runtime.h>

#define NWORDS 100000
#define NQ 50
#define NS 64

// Heads table, full 3-component quad layout: per (q, sq) 12 floats =
//   h0[s..s+3], h1[s..s+3], h2[s..s+3]   (three 16B groups)
__device__ __align__(16) float g_hH[NQ * 16 * 12];
__device__ __align__(8)  float g_hr[NS];
__device__ double g_acc;

typedef unsigned long long u64;

__device__ __forceinline__ u64 bc2(float x) {
    u64 r; asm("mov.b64 %0, {%1, %1};" : "=l"(r) : "f"(x)); return r;
}
__device__ __forceinline__ u64 fma2(u64 a, u64 b, u64 c) {
    u64 d; asm("fma.rn.f32x2 %0, %1, %2, %3;" : "=l"(d) : "l"(a), "l"(b), "l"(c)); return d;
}
__device__ __forceinline__ u64 mul2(u64 a, u64 b) {
    u64 d; asm("mul.rn.f32x2 %0, %1, %2;" : "=l"(d) : "l"(a), "l"(b)); return d;
}
__device__ __forceinline__ void up2(u64 a, float& x, float& y) {
    asm("mov.b64 {%0, %1}, %2;" : "=f"(x), "=f"(y) : "l"(a));
}

// softplus(20x) = max(y,0) + log1p(exp(-|y|))
__device__ __forceinline__ float sp20(float x) {
    float y = 20.0f * x;
    return fmaxf(y, 0.0f) + log1pf(expf(-fabsf(y)));
}

__global__ void setup_kernel(const float* __restrict__ hp, const float* __restrict__ hrp) {
    int tid = threadIdx.x;
    if (blockIdx.x == 0) {
        __shared__ float sv[NS];
        __shared__ float ssum;
        if (tid == 0) g_acc = 0.0;
        if (tid < NS) sv[tid] = sp20(hrp[tid]);
        __syncthreads();
        if (tid == 0) {
            float s = 0.0f;
            for (int i = 0; i < NS; i++) s += sv[i];
            ssum = fmaxf(s, 1e-12f);
        }
        __syncthreads();
        if (tid < NS) g_hr[tid] = (sv[tid] / ssum + 0.001f / (float)NS) / 1.001f;
    }
    int idx = blockIdx.x * blockDim.x + tid;
    if (idx < NS * NQ) {
        int q = idx >> 6;
        int s = idx & 63;
        const float* p = hp + ((size_t)s * NQ + q) * 3;
        float v0 = sp20(p[0]);
        float v1 = sp20(p[1]);
        float v2 = sp20(p[2]);
        float sm = fmaxf((v0 + v1) + v2, 1e-12f);
        int sq = s >> 2, r = s & 3;
        float* g = g_hH + ((size_t)q * 16 + sq) * 12;
        g[r]     = v0 / sm;
        g[4 + r] = v1 / sm;
        g[8 + r] = v2 / sm;
    }
}

// Thread = (n-quad, s-quarter).  256 threads/block -> 256 n per block.
// smem: heads table (9600 f, 38.4KB) + transposed 10-q tile (30 x 264 f, 31.7KB)
#define SH_HEADS 9600
#define SH_TROW  264
#define SMEM_FLOATS (SH_HEADS + 30 * SH_TROW)

__global__ __launch_bounds__(256, 2)
void cov_kernel(const float* __restrict__ tpl, const float* __restrict__ coeff) {
    extern __shared__ __align__(16) float smem[];
    float* sH = smem;
    float* sT = smem + SH_HEADS;

    const int tid   = threadIdx.x;
    const int qt    = tid & 3;          // s-quarter 0..3 (16 heads each)
    const int nq    = tid >> 2;         // n-quad 0..63
    const int nBase = blockIdx.x * 256;

    // stage heads table (38.4 KB) once per block
    {
        const float4* src = (const float4*)g_hH;
        float4* dst = (float4*)sH;
        for (int i = tid; i < SH_HEADS / 4; i += 256) dst[i] = src[i];
    }

    const u64 ONE = 0x3f8000003f800000ULL;
    u64 prod[8][4];
#pragma unroll
    for (int j = 0; j < 8; j++)
#pragma unroll
        for (int n = 0; n < 4; n++) prod[j][n] = ONE;

#pragma unroll 1
    for (int qc = 0; qc < NQ; qc += 10) {
        __syncthreads();   // covers heads staging (first iter) and sT reuse
        // stage 256 rows x 30 floats (coalesced float2), transposed into sT
        for (int i = tid; i < 256 * 15; i += 256) {
            int nl = i / 15;
            int j2 = i - nl * 15;
            int n  = nBase + nl;
            n = (n < NWORDS) ? n : (NWORDS - 1);
            float2 v = *(const float2*)(tpl + (size_t)n * (NQ * 3) + (size_t)(qc * 3 + j2 * 2));
            int jj = j2 * 2;
            sT[jj * SH_TROW + nl]       = v.x;
            sT[(jj + 1) * SH_TROW + nl] = v.y;
        }
        __syncthreads();

#pragma unroll
        for (int qq = 0; qq < 10; qq++) {
            const float* tb = sT + (qq * 3) * SH_TROW + nq * 4;
            float4 r0 = *(const float4*)(tb);
            float4 r1 = *(const float4*)(tb + SH_TROW);
            float4 r2 = *(const float4*)(tb + 2 * SH_TROW);
            u64 T0[4], T1[4], T2[4];
            T0[0] = bc2(r0.x); T0[1] = bc2(r0.y); T0[2] = bc2(r0.z); T0[3] = bc2(r0.w);
            T1[0] = bc2(r1.x); T1[1] = bc2(r1.y); T1[2] = bc2(r1.z); T1[3] = bc2(r1.w);
            T2[0] = bc2(r2.x); T2[1] = bc2(r2.y); T2[2] = bc2(r2.z); T2[3] = bc2(r2.w);
            // cell = 12 floats = 3 ulonglong2
            const ulonglong2* hb =
                (const ulonglong2*)sH + ((size_t)(qc + qq) * 16 + qt * 4) * 3;
#pragma unroll
            for (int j = 0; j < 4; j++) {
                ulonglong2 A = hb[3 * j];       // h0 pairs (broadcast LDS.128)
                ulonglong2 B = hb[3 * j + 1];   // h1 pairs
                ulonglong2 C = hb[3 * j + 2];   // h2 pairs
#pragma unroll
                for (int n = 0; n < 4; n++) {
                    u64 a = mul2(C.x, T2[n]);
                    a = fma2(B.x, T1[n], a);
                    a = fma2(A.x, T0[n], a);
                    prod[2 * j][n] = mul2(prod[2 * j][n], a);
                    u64 b = mul2(C.y, T2[n]);
                    b = fma2(B.y, T1[n], b);
                    b = fma2(A.y, T0[n], b);
                    prod[2 * j + 1][n] = mul2(prod[2 * j + 1][n], b);
                }
            }
        }
    }

    // ratio-weighted partial covs for this thread's 4 n over its 16 heads
    float cov[4] = {0.f, 0.f, 0.f, 0.f};
#pragma unroll
    for (int p = 0; p < 8; p++) {
        float2 w = *(const float2*)(g_hr + (size_t)(qt * 8 + p) * 2);
#pragma unroll
        for (int n = 0; n < 4; n++) {
            float lo, hi;
            up2(prod[p][n], lo, hi);
            cov[n] = fmaf(w.x, lo, cov[n]);
            cov[n] = fmaf(w.y, hi, cov[n]);
        }
    }
    // combine the 4 s-quarters (adjacent lanes share nq)
#pragma unroll
    for (int o = 1; o <= 2; o <<= 1)
#pragma unroll
        for (int n = 0; n < 4; n++)
            cov[n] += __shfl_xor_sync(0xffffffffu, cov[n], o);

    double term = 0.0;
    if (qt == 0) {
        int n0 = nBase + nq * 4;
#pragma unroll
        for (int k = 0; k < 4; k++) {
            if (n0 + k < NWORDS) {
                float c = coeff[n0 + k];
                term += ((double)c * (double)c) / (double)cov[k];
            }
        }
    }
#pragma unroll
    for (int o = 16; o > 0; o >>= 1)
        term += __shfl_down_sync(0xffffffffu, term, o);
    if ((tid & 31) == 0) atomicAdd(&g_acc, term);
}

__global__ void fin_kernel(float* out) {
    out[0] = (float)g_acc;
}

extern "C" void kernel_launch(void* const* d_in, const int* in_sizes, int n_in,
                              void* d_out, int out_size) {
    const float* tpl = (const float*)d_in[0];   // batch_pauli_tensor [N,Q,P] f32
    const float* cf  = (const float*)d_in[1];   // batch_coeff [N]
    const float* hp  = (const float*)d_in[2];   // heads_param [S,Q,P]
    const float* hrp = (const float*)d_in[3];   // head_ratios_param [S]

    cudaFuncSetAttribute(cov_kernel, cudaFuncAttributeMaxDynamicSharedMemorySize,
                         SMEM_FLOATS * sizeof(float));

    setup_kernel<<<13, 256>>>(hp, hrp);
    cov_kernel<<<(NWORDS + 255) / 256, 256, SMEM_FLOATS * sizeof(float)>>>(tpl, cf);
    fin_kernel<<<1, 1>>>((float*)d_out);
}

// round 6
// speedup vs baseline: 2.2333x; 2.2333x over previous
#include <cuda_runtime.h>

#define NWORDS 100000
#define NQ 50
#define NS 64
#define NBLOCKS 782   // ceil(100000 / 128)

// Heads table, quad layout: per (q, sq) 12 floats = h0[s..s+3], h1[s..s+3], h2[s..s+3]
__device__ __align__(16) float g_hH[NQ * 16 * 12];
__device__ __align__(8)  float g_hr[NS];
__device__ double g_acc = 0.0;
__device__ unsigned int g_counter = 0u;

typedef unsigned long long u64;

__device__ __forceinline__ u64 bc2(float x) {
    u64 r; asm("mov.b64 %0, {%1, %1};" : "=l"(r) : "f"(x)); return r;
}
__device__ __forceinline__ u64 fma2(u64 a, u64 b, u64 c) {
    u64 d; asm("fma.rn.f32x2 %0, %1, %2, %3;" : "=l"(d) : "l"(a), "l"(b), "l"(c)); return d;
}
__device__ __forceinline__ u64 mul2(u64 a, u64 b) {
    u64 d; asm("mul.rn.f32x2 %0, %1, %2;" : "=l"(d) : "l"(a), "l"(b)); return d;
}
__device__ __forceinline__ void up2(u64 a, float& x, float& y) {
    asm("mov.b64 {%0, %1}, %2;" : "=f"(x), "=f"(y) : "l"(a));
}

__device__ __forceinline__ float sp20(float x) {
    float y = 20.0f * x;
    return fmaxf(y, 0.0f) + log1pf(expf(-fabsf(y)));
}

__global__ void setup_kernel(const float* __restrict__ hp, const float* __restrict__ hrp) {
    int tid = threadIdx.x;
    if (blockIdx.x == 0) {
        __shared__ float sv[NS];
        __shared__ float ssum;
        if (tid < NS) sv[tid] = sp20(hrp[tid]);
        __syncthreads();
        if (tid == 0) {
            float s = 0.0f;
            for (int i = 0; i < NS; i++) s += sv[i];
            ssum = fmaxf(s, 1e-12f);
        }
        __syncthreads();
        if (tid < NS) g_hr[tid] = (sv[tid] / ssum + 0.001f / (float)NS) / 1.001f;
    }
    int idx = blockIdx.x * blockDim.x + tid;
    if (idx < NS * NQ) {
        int q = idx >> 6;
        int s = idx & 63;
        const float* p = hp + ((size_t)s * NQ + q) * 3;
        float v0 = sp20(p[0]);
        float v1 = sp20(p[1]);
        float v2 = sp20(p[2]);
        float sm = fmaxf((v0 + v1) + v2, 1e-12f);
        int sq = s >> 2, r = s & 3;
        float* g = g_hH + ((size_t)q * 16 + sq) * 12;
        g[r]     = v0 / sm;
        g[4 + r] = v1 / sm;
        g[8 + r] = v2 / sm;
    }
}

// Thread = (n-quad, s-octant). 256 threads -> 32 n-quads (128 n) x 8 s-groups.
// Each thread: 4 n, 8 heads (2 quads = 4 f32x2 pairs) -> prod[4][4] u64 (32 regs).
// smem: heads table 9600 f (38.4KB) + transposed 10-q tile 30 x 132 f (15.8KB)
#define SH_HEADS 9600
#define SH_TROW  132
#define SMEM_FLOATS (SH_HEADS + 30 * SH_TROW)

__global__ __launch_bounds__(256, 3)
void cov_kernel(const float* __restrict__ tpl, const float* __restrict__ coeff,
                float* __restrict__ out) {
    extern __shared__ __align__(16) float smem[];
    float* sH = smem;
    float* sT = smem + SH_HEADS;

    const int tid   = threadIdx.x;
    const int qt    = tid & 7;          // s-octant 0..7 (8 heads each)
    const int nq    = tid >> 3;         // n-quad 0..31
    const int nBase = blockIdx.x * 128;

    // stage heads table (38.4 KB) once per block
    {
        const float4* src = (const float4*)g_hH;
        float4* dst = (float4*)sH;
        for (int i = tid; i < SH_HEADS / 4; i += 256) dst[i] = src[i];
    }

    const u64 ONE = 0x3f8000003f800000ULL;
    u64 prod[4][4];
#pragma unroll
    for (int p = 0; p < 4; p++)
#pragma unroll
        for (int n = 0; n < 4; n++) prod[p][n] = ONE;

#pragma unroll 1
    for (int qc = 0; qc < NQ; qc += 10) {
        __syncthreads();   // heads staging (1st iter) / sT reuse
        // stage 128 rows x 30 floats (coalesced float2), transposed into sT
        for (int i = tid; i < 128 * 15; i += 256) {
            int nl = i / 15;
            int j2 = i - nl * 15;
            int n  = nBase + nl;
            n = (n < NWORDS) ? n : (NWORDS - 1);
            float2 v = *(const float2*)(tpl + (size_t)n * (NQ * 3) + (size_t)(qc * 3 + j2 * 2));
            int jj = j2 * 2;
            sT[jj * SH_TROW + nl]       = v.x;
            sT[(jj + 1) * SH_TROW + nl] = v.y;
        }
        __syncthreads();

#pragma unroll 2
        for (int qq = 0; qq < 10; qq++) {
            const float* tb = sT + (qq * 3) * SH_TROW + nq * 4;
            float4 r0 = *(const float4*)(tb);
            float4 r1 = *(const float4*)(tb + SH_TROW);
            float4 r2 = *(const float4*)(tb + 2 * SH_TROW);
            u64 T0[4], T1[4], T2[4];
            T0[0] = bc2(r0.x); T0[1] = bc2(r0.y); T0[2] = bc2(r0.z); T0[3] = bc2(r0.w);
            T1[0] = bc2(r1.x); T1[1] = bc2(r1.y); T1[2] = bc2(r1.z); T1[3] = bc2(r1.w);
            T2[0] = bc2(r2.x); T2[1] = bc2(r2.y); T2[2] = bc2(r2.z); T2[3] = bc2(r2.w);
            // this thread's 2 head-quads for this q
            const ulonglong2* hb =
                (const ulonglong2*)sH + ((size_t)(qc + qq) * 16 + qt * 2) * 3;
#pragma unroll
            for (int j = 0; j < 2; j++) {
                ulonglong2 A = hb[3 * j];       // h0 pairs
                ulonglong2 B = hb[3 * j + 1];   // h1 pairs
                ulonglong2 C = hb[3 * j + 2];   // h2 pairs
#pragma unroll
                for (int n = 0; n < 4; n++) {
                    u64 a = mul2(C.x, T2[n]);
                    a = fma2(B.x, T1[n], a);
                    a = fma2(A.x, T0[n], a);
                    prod[2 * j][n] = mul2(prod[2 * j][n], a);
                    u64 b = mul2(C.y, T2[n]);
                    b = fma2(B.y, T1[n], b);
                    b = fma2(A.y, T0[n], b);
                    prod[2 * j + 1][n] = mul2(prod[2 * j + 1][n], b);
                }
            }
        }
    }

    // ratio-weighted partial covs for this thread's 4 n over its 8 heads
    float cov[4] = {0.f, 0.f, 0.f, 0.f};
#pragma unroll
    for (int p = 0; p < 4; p++) {
        float2 w = *(const float2*)(g_hr + (size_t)qt * 8 + p * 2);
#pragma unroll
        for (int n = 0; n < 4; n++) {
            float lo, hi;
            up2(prod[p][n], lo, hi);
            cov[n] = fmaf(w.x, lo, cov[n]);
            cov[n] = fmaf(w.y, hi, cov[n]);
        }
    }
    // combine the 8 s-octants (8 consecutive lanes share an n-quad)
#pragma unroll
    for (int o = 1; o <= 4; o <<= 1)
#pragma unroll
        for (int n = 0; n < 4; n++)
            cov[n] += __shfl_xor_sync(0xffffffffu, cov[n], o);

    double term = 0.0;
    if (qt == 0) {
        int n0 = nBase + nq * 4;
#pragma unroll
        for (int k = 0; k < 4; k++) {
            if (n0 + k < NWORDS) {
                float c = coeff[n0 + k];
                term += ((double)c * (double)c) / (double)cov[k];
            }
        }
    }
#pragma unroll
    for (int o = 16; o > 0; o >>= 1)
        term += __shfl_down_sync(0xffffffffu, term, o);

    __shared__ double sAcc[8];
    if ((tid & 31) == 0) sAcc[tid >> 5] = term;
    __syncthreads();
    if (tid == 0) {
        double t = 0.0;
#pragma unroll
        for (int w = 0; w < 8; w++) t += sAcc[w];
        atomicAdd(&g_acc, t);
        __threadfence();
        unsigned int done = atomicAdd(&g_counter, 1u);
        if (done == NBLOCKS - 1) {
            // last block: publish result, reset state for next replay
            out[0] = (float)g_acc;
            g_acc = 0.0;
            g_counter = 0u;
        }
    }
}

extern "C" void kernel_launch(void* const* d_in, const int* in_sizes, int n_in,
                              void* d_out, int out_size) {
    const float* tpl = (const float*)d_in[0];   // batch_pauli_tensor [N,Q,P] f32
    const float* cf  = (const float*)d_in[1];   // batch_coeff [N]
    const float* hp  = (const float*)d_in[2];   // heads_param [S,Q,P]
    const float* hrp = (const float*)d_in[3];   // head_ratios_param [S]

    cudaFuncSetAttribute(cov_kernel, cudaFuncAttributeMaxDynamicSharedMemorySize,
                         SMEM_FLOATS * sizeof(float));

    setup_kernel<<<13, 256>>>(hp, hrp);
    cov_kernel<<<NBLOCKS, 256, SMEM_FLOATS * sizeof(float)>>>(tpl, cf, (float*)d_out);
}

// round 7
// speedup vs baseline: 2.7991x; 1.2534x over previous
#include <cuda_runtime.h>

#define NWORDS 100000
#define NQ 50
#define NS 64
#define NBLOCKS 782   // ceil(100000 / 128)

// Heads table, padded octant layout: per (q, qt) cell of 28 floats (112B stride):
//   [h0 quad j0][h1 quad j0][h2 quad j0][h0 quad j1][h1 quad j1][h2 quad j1][pad 4]
// 112B stride => cell base bank = qt*28 mod 32, all 8 distinct -> conflict-free LDS.128
__device__ __align__(16) float g_hH[NQ * 8 * 28];
__device__ __align__(8)  float g_hr[NS];
__device__ double g_acc = 0.0;
__device__ unsigned int g_counter = 0u;

typedef unsigned long long u64;

__device__ __forceinline__ u64 bc2(float x) {
    u64 r; asm("mov.b64 %0, {%1, %1};" : "=l"(r) : "f"(x)); return r;
}
__device__ __forceinline__ u64 fma2(u64 a, u64 b, u64 c) {
    u64 d; asm("fma.rn.f32x2 %0, %1, %2, %3;" : "=l"(d) : "l"(a), "l"(b), "l"(c)); return d;
}
__device__ __forceinline__ u64 mul2(u64 a, u64 b) {
    u64 d; asm("mul.rn.f32x2 %0, %1, %2;" : "=l"(d) : "l"(a), "l"(b)); return d;
}
__device__ __forceinline__ void up2(u64 a, float& x, float& y) {
    asm("mov.b64 {%0, %1}, %2;" : "=f"(x), "=f"(y) : "l"(a));
}

__device__ __forceinline__ float sp20(float x) {
    float y = 20.0f * x;
    return fmaxf(y, 0.0f) + log1pf(expf(-fabsf(y)));
}

__global__ void setup_kernel(const float* __restrict__ hp, const float* __restrict__ hrp) {
    int tid = threadIdx.x;
    if (blockIdx.x == 0) {
        __shared__ float sv[NS];
        __shared__ float ssum;
        if (tid < NS) sv[tid] = sp20(hrp[tid]);
        __syncthreads();
        if (tid == 0) {
            float s = 0.0f;
            for (int i = 0; i < NS; i++) s += sv[i];
            ssum = fmaxf(s, 1e-12f);
        }
        __syncthreads();
        if (tid < NS) g_hr[tid] = (sv[tid] / ssum + 0.001f / (float)NS) / 1.001f;
    }
    int idx = blockIdx.x * blockDim.x + tid;
    if (idx < NS * NQ) {
        int q = idx >> 6;
        int s = idx & 63;
        const float* p = hp + ((size_t)s * NQ + q) * 3;
        float v0 = sp20(p[0]);
        float v1 = sp20(p[1]);
        float v2 = sp20(p[2]);
        float sm = fmaxf((v0 + v1) + v2, 1e-12f);
        int qt = s >> 3, j = (s >> 2) & 1, r = s & 3;
        float* g = g_hH + ((size_t)q * 8 + qt) * 28 + j * 12;
        g[r]     = v0 / sm;
        g[4 + r] = v1 / sm;
        g[8 + r] = v2 / sm;
    }
}

// Thread = (n-quad, s-octant). 256 threads -> 32 n-quads (128 n) x 8 s-octants.
// smem: heads table 11200 f (44.8KB) + transposed 10-q tile 30 x 132 f (15.8KB)
#define SH_HEADS 11200
#define SH_TROW  132
#define SMEM_FLOATS (SH_HEADS + 30 * SH_TROW)

__global__ __launch_bounds__(256, 3)
void cov_kernel(const float* __restrict__ tpl, const float* __restrict__ coeff,
                float* __restrict__ out) {
    extern __shared__ __align__(16) float smem[];
    float* sH = smem;
    float* sT = smem + SH_HEADS;

    const int tid   = threadIdx.x;
    const int qt    = tid & 7;          // s-octant 0..7 (8 heads each)
    const int nq    = tid >> 3;         // n-quad 0..31
    const int nBase = blockIdx.x * 128;

    // stage heads table (44.8 KB) once per block
    {
        const float4* src = (const float4*)g_hH;
        float4* dst = (float4*)sH;
        for (int i = tid; i < SH_HEADS / 4; i += 256) dst[i] = src[i];
    }

    const u64 ONE = 0x3f8000003f800000ULL;
    u64 prod[4][4];
#pragma unroll
    for (int p = 0; p < 4; p++)
#pragma unroll
        for (int n = 0; n < 4; n++) prod[p][n] = ONE;

#pragma unroll 1
    for (int qc = 0; qc < NQ; qc += 10) {
        __syncthreads();   // heads staging (1st iter) / sT reuse
        // stage 128 rows x 30 floats (coalesced float2), transposed into sT
        for (int i = tid; i < 128 * 15; i += 256) {
            int nl = i / 15;
            int j2 = i - nl * 15;
            int n  = nBase + nl;
            n = (n < NWORDS) ? n : (NWORDS - 1);
            float2 v = *(const float2*)(tpl + (size_t)n * (NQ * 3) + (size_t)(qc * 3 + j2 * 2));
            int jj = j2 * 2;
            sT[jj * SH_TROW + nl]       = v.x;
            sT[(jj + 1) * SH_TROW + nl] = v.y;
        }
        __syncthreads();

#pragma unroll 2
        for (int qq = 0; qq < 10; qq++) {
            // conflict-free heads cell: 112B stride across the 8 octant lanes
            const ulonglong2* hb =
                (const ulonglong2*)(sH + ((size_t)(qc + qq) * 8 + qt) * 28);
            ulonglong2 A0 = hb[0], B0 = hb[1], C0 = hb[2];
            ulonglong2 A1 = hb[3], B1 = hb[4], C1 = hb[5];

            const float* tb = sT + (qq * 3) * SH_TROW + nq * 4;
            float4 r0 = *(const float4*)(tb);
            float4 r1 = *(const float4*)(tb + SH_TROW);
            float4 r2 = *(const float4*)(tb + 2 * SH_TROW);
            u64 T0[4], T1[4], T2[4];
            T0[0] = bc2(r0.x); T0[1] = bc2(r0.y); T0[2] = bc2(r0.z); T0[3] = bc2(r0.w);
            T1[0] = bc2(r1.x); T1[1] = bc2(r1.y); T1[2] = bc2(r1.z); T1[3] = bc2(r1.w);
            T2[0] = bc2(r2.x); T2[1] = bc2(r2.y); T2[2] = bc2(r2.z); T2[3] = bc2(r2.w);

#pragma unroll
            for (int n = 0; n < 4; n++) {
                u64 a = mul2(C0.x, T2[n]);
                a = fma2(B0.x, T1[n], a);
                a = fma2(A0.x, T0[n], a);
                prod[0][n] = mul2(prod[0][n], a);
                u64 b = mul2(C0.y, T2[n]);
                b = fma2(B0.y, T1[n], b);
                b = fma2(A0.y, T0[n], b);
                prod[1][n] = mul2(prod[1][n], b);
                u64 c = mul2(C1.x, T2[n]);
                c = fma2(B1.x, T1[n], c);
                c = fma2(A1.x, T0[n], c);
                prod[2][n] = mul2(prod[2][n], c);
                u64 d = mul2(C1.y, T2[n]);
                d = fma2(B1.y, T1[n], d);
                d = fma2(A1.y, T0[n], d);
                prod[3][n] = mul2(prod[3][n], d);
            }
        }
    }

    // ratio-weighted partial covs for this thread's 4 n over its 8 heads
    // prod[p] covers heads s = qt*8 + p*2 (pairs: p=0 -> s0,s1 ... within quads j)
    // mapping: p=0 -> (qt*8+0, qt*8+1), p=1 -> (+2,+3), p=2 -> (+4,+5), p=3 -> (+6,+7)
    float cov[4] = {0.f, 0.f, 0.f, 0.f};
#pragma unroll
    for (int p = 0; p < 4; p++) {
        float2 w = *(const float2*)(g_hr + (size_t)qt * 8 + p * 2);
#pragma unroll
        for (int n = 0; n < 4; n++) {
            float lo, hi;
            up2(prod[p][n], lo, hi);
            cov[n] = fmaf(w.x, lo, cov[n]);
            cov[n] = fmaf(w.y, hi, cov[n]);
        }
    }
    // combine the 8 s-octants (8 consecutive lanes share an n-quad)
#pragma unroll
    for (int o = 1; o <= 4; o <<= 1)
#pragma unroll
        for (int n = 0; n < 4; n++)
            cov[n] += __shfl_xor_sync(0xffffffffu, cov[n], o);

    double term = 0.0;
    if (qt == 0) {
        int n0 = nBase + nq * 4;
#pragma unroll
        for (int k = 0; k < 4; k++) {
            if (n0 + k < NWORDS) {
                float c = coeff[n0 + k];
                term += ((double)c * (double)c) / (double)cov[k];
            }
        }
    }
#pragma unroll
    for (int o = 16; o > 0; o >>= 1)
        term += __shfl_down_sync(0xffffffffu, term, o);

    __shared__ double sAcc[8];
    if ((tid & 31) == 0) sAcc[tid >> 5] = term;
    __syncthreads();
    if (tid == 0) {
        double t = 0.0;
#pragma unroll
        for (int w = 0; w < 8; w++) t += sAcc[w];
        atomicAdd(&g_acc, t);
        __threadfence();
        unsigned int done = atomicAdd(&g_counter, 1u);
        if (done == NBLOCKS - 1) {
            out[0] = (float)g_acc;
            g_acc = 0.0;
            g_counter = 0u;
        }
    }
}

extern "C" void kernel_launch(void* const* d_in, const int* in_sizes, int n_in,
                              void* d_out, int out_size) {
    const float* tpl = (const float*)d_in[0];   // batch_pauli_tensor [N,Q,P] f32
    const float* cf  = (const float*)d_in[1];   // batch_coeff [N]
    const float* hp  = (const float*)d_in[2];   // heads_param [S,Q,P]
    const float* hrp = (const float*)d_in[3];   // head_ratios_param [S]

    cudaFuncSetAttribute(cov_kernel, cudaFuncAttributeMaxDynamicSharedMemorySize,
                         SMEM_FLOATS * sizeof(float));

    setup_kernel<<<13, 256>>>(hp, hrp);
    cov_kernel<<<NBLOCKS, 256, SMEM_FLOATS * sizeof(float)>>>(tpl, cf, (float*)d_out);
}